// round 3
// baseline (speedup 1.0000x reference)
#include <cuda_runtime.h>
#include <cuda_fp16.h>
#include <math.h>
#include <stdint.h>

#define BB 64      // batch
#define TT 512     // seq len
#define DD 512     // input size
#define HH 1024    // hidden size
#define GG 4096    // 4*H

// ---------------------------------------------------------------------------
// Global scratch
// ---------------------------------------------------------------------------
// xz permuted: [dir][t][b][p] with p = j*4 + g (gate-interleaved)
__device__ float g_xz[(size_t)2 * TT * BB * GG];
// Wh fp16 split, fragment-native order for mma.sync m16n8k16 B operand:
// [dir][mat(hi/lo)][ntile(512)][kchunk(64)][lane(32)] : uint2 (4 halfs)
__device__ uint2 g_Wfrag[(size_t)2 * 2 * 512 * 64 * 32];
// h fp16 split, row-major: [parity][dir][mat][b(64)][k(1024)]
__device__ __half g_A[(size_t)2 * 2 * 2 * 64 * 1024];
// cell state: [dir][b][j]
__device__ float g_c[2 * BB * HH];

// ---------------------------------------------------------------------------
#define MMA16816(d, a0, a1, a2, a3, b0, b1)                                  \
    asm volatile(                                                            \
        "mma.sync.aligned.m16n8k16.row.col.f32.f16.f16.f32 "                 \
        "{%0,%1,%2,%3}, {%4,%5,%6,%7}, {%8,%9}, {%0,%1,%2,%3};"              \
        : "+f"((d)[0]), "+f"((d)[1]), "+f"((d)[2]), "+f"((d)[3])             \
        : "r"(a0), "r"(a1), "r"(a2), "r"(a3), "r"(b0), "r"(b1))

// ---------------------------------------------------------------------------
// Init: zero c and A parity-0 image
// ---------------------------------------------------------------------------
__global__ void init_kernel() {
    int i = blockIdx.x * blockDim.x + threadIdx.x;   // 0..131071
    g_c[i] = 0.0f;
    ((uint32_t*)g_A)[i] = 0u;   // first 524288 bytes = parity 0
}

// ---------------------------------------------------------------------------
// Weight conversion: Wh fp32 -> fp16 hi/lo in B-fragment order (one-time).
// Fragment (m16n8k16 B, col): lane holds (k = (lane%4)*2+{0,1}, n = lane/4)
// and same with k+8. Column n here is the PERMUTED column p = j*4+g.
// ---------------------------------------------------------------------------
__global__ void conv_kernel(const float* __restrict__ Whf,
                            const float* __restrict__ Whb) {
    int idx = blockIdx.x * blockDim.x + threadIdx.x;   // 0 .. 2^21-1
    int lane = idx & 31;
    int kc   = (idx >> 5) & 63;
    int nt   = (idx >> 11) & 511;
    int dir  = idx >> 20;
    const float* W = dir ? Whb : Whf;

    int p   = nt * 8 + (lane >> 2);          // permuted col
    int col = ((p & 3) << 10) + (p >> 2);    // original gate-major col
    int k0  = kc * 16 + (lane & 3) * 2;

    float w0 = W[(size_t)(k0)     * GG + col];
    float w1 = W[(size_t)(k0 + 1) * GG + col];
    float w2 = W[(size_t)(k0 + 8) * GG + col];
    float w3 = W[(size_t)(k0 + 9) * GG + col];

    __half h0 = __float2half_rn(w0), h1 = __float2half_rn(w1);
    __half h2 = __float2half_rn(w2), h3 = __float2half_rn(w3);
    __half l0 = __float2half_rn(w0 - __half2float(h0));
    __half l1 = __float2half_rn(w1 - __half2float(h1));
    __half l2 = __float2half_rn(w2 - __half2float(h2));
    __half l3 = __float2half_rn(w3 - __half2float(h3));

    uint2 hi, lo;
    hi.x = (uint32_t)__half_as_ushort(h0) | ((uint32_t)__half_as_ushort(h1) << 16);
    hi.y = (uint32_t)__half_as_ushort(h2) | ((uint32_t)__half_as_ushort(h3) << 16);
    lo.x = (uint32_t)__half_as_ushort(l0) | ((uint32_t)__half_as_ushort(l1) << 16);
    lo.y = (uint32_t)__half_as_ushort(l2) | ((uint32_t)__half_as_ushort(l3) << 16);

    size_t o_hi = ((((size_t)dir * 2 + 0) * 512 + nt) * 64 + kc) * 32 + lane;
    size_t o_lo = ((((size_t)dir * 2 + 1) * 512 + nt) * 64 + kc) * 32 + lane;
    g_Wfrag[o_hi] = hi;
    g_Wfrag[o_lo] = lo;
}

// ---------------------------------------------------------------------------
// Input projection (fp32 SGEMM, permuted epilogue -> g_xz)
// ---------------------------------------------------------------------------
__global__ void proj_kernel(const float* __restrict__ X,
                            const float* __restrict__ Wxf,
                            const float* __restrict__ Wxb,
                            const float* __restrict__ bf,
                            const float* __restrict__ bb) {
    const int dir = blockIdx.z;
    const float* __restrict__ W    = dir ? Wxb : Wxf;
    const float* __restrict__ bias = dir ? bb : bf;
    const int n0 = blockIdx.x * 128;
    const int m0 = blockIdx.y * 128;

    __shared__ float As[8][128];
    __shared__ float Bs[8][128];

    const int tid = threadIdx.x;
    const int tx = tid & 15;
    const int ty = tid >> 4;
    const int arow = tid >> 1;
    const int acol = (tid & 1) << 2;
    const int bk   = tid >> 5;
    const int bcol = (tid & 31) << 2;

    float acc[8][8];
#pragma unroll
    for (int i = 0; i < 8; i++)
#pragma unroll
        for (int j = 0; j < 8; j++) acc[i][j] = 0.0f;

    for (int k0 = 0; k0 < DD; k0 += 8) {
        float4 av = *(const float4*)(X + (size_t)(m0 + arow) * DD + k0 + acol);
        As[acol + 0][arow] = av.x;
        As[acol + 1][arow] = av.y;
        As[acol + 2][arow] = av.z;
        As[acol + 3][arow] = av.w;
        *(float4*)(&Bs[bk][bcol]) =
            *(const float4*)(W + (size_t)(k0 + bk) * GG + n0 + bcol);
        __syncthreads();
#pragma unroll
        for (int kk = 0; kk < 8; kk++) {
            float a[8], b[8];
            *(float4*)(a)     = *(float4*)(&As[kk][ty * 8]);
            *(float4*)(a + 4) = *(float4*)(&As[kk][ty * 8 + 4]);
            *(float4*)(b)     = *(float4*)(&Bs[kk][tx * 8]);
            *(float4*)(b + 4) = *(float4*)(&Bs[kk][tx * 8 + 4]);
#pragma unroll
            for (int i = 0; i < 8; i++)
#pragma unroll
                for (int j = 0; j < 8; j++)
                    acc[i][j] = fmaf(a[i], b[j], acc[i][j]);
        }
        __syncthreads();
    }

    float bv[8];
#pragma unroll
    for (int j = 0; j < 8; j++) bv[j] = bias[n0 + tx * 8 + j];

#pragma unroll
    for (int i = 0; i < 8; i++) {
        int m  = m0 + ty * 8 + i;
        int bi = m >> 9;
        int tt = m & (TT - 1);
        float* dst = g_xz + (((size_t)dir * TT + tt) * BB + bi) * GG;
#pragma unroll
        for (int j = 0; j < 8; j++) {
            int nf = n0 + tx * 8 + j;                   // gate-major col
            int p  = ((nf & 1023) << 2) | (nf >> 10);   // permuted col
            dst[p] = acc[i][j] + bv[j];
        }
    }
}

// ---------------------------------------------------------------------------
// Recurrence step: mma.sync fp16 3-term split. grid (64, 2), 256 threads.
// CTA covers 64 permuted cols (16 hidden units); warp w covers 8 cols (ntile).
// z[64 x 64] = h[64 x 1024] @ W_tile (split: AhBh + AhBl + AlBh).
// ---------------------------------------------------------------------------
__global__ void __launch_bounds__(256, 1) step_kernel(int s, float* __restrict__ out) {
    const int dir  = blockIdx.y;
    const int nblk = blockIdx.x;
    const int t  = dir ? (TT - 1 - s) : s;
    const int pr = s & 1;
    const int pw = pr ^ 1;
    const int warp = threadIdx.x >> 5;
    const int lane = threadIdx.x & 31;
    const int qr = lane >> 2;
    const int qc = lane & 3;
    const int ntg = nblk * 8 + warp;

    const __half* Ah = g_A + ((size_t)(pr * 2 + dir) * 2 + 0) * 65536;
    const __half* Al = Ah + 65536;
    const uint2* Bh = g_Wfrag + (((size_t)(dir * 2 + 0) * 512 + ntg) * 64) * 32 + lane;
    const uint2* Bl = g_Wfrag + (((size_t)(dir * 2 + 1) * 512 + ntg) * 64) * 32 + lane;

    float d[4][4] = {};

    const __half* a_base = Ah + (size_t)qr * 1024 + qc * 2;
    const __half* l_base = Al + (size_t)qr * 1024 + qc * 2;

#pragma unroll 2
    for (int kc = 0; kc < 64; kc++) {
        const uint2 bh = Bh[kc * 32];
        const uint2 bl = Bl[kc * 32];
        const int k0 = kc * 16;
#pragma unroll
        for (int mt = 0; mt < 4; mt++) {
            const __half* ap = a_base + (size_t)mt * 16 * 1024 + k0;
            uint32_t a0 = *(const uint32_t*)(ap);
            uint32_t a1 = *(const uint32_t*)(ap + 8 * 1024);
            uint32_t a2 = *(const uint32_t*)(ap + 8);
            uint32_t a3 = *(const uint32_t*)(ap + 8 * 1024 + 8);
            MMA16816(d[mt], a0, a1, a2, a3, bh.x, bh.y);
            MMA16816(d[mt], a0, a1, a2, a3, bl.x, bl.y);
            const __half* lp = l_base + (size_t)mt * 16 * 1024 + k0;
            uint32_t l0 = *(const uint32_t*)(lp);
            uint32_t l1 = *(const uint32_t*)(lp + 8 * 1024);
            uint32_t l2 = *(const uint32_t*)(lp + 8);
            uint32_t l3 = *(const uint32_t*)(lp + 8 * 1024 + 8);
            MMA16816(d[mt], l0, l1, l2, l3, bh.x, bh.y);
        }
    }

    // --- Epilogue: pair lanes (xor 1) to gather 4 gates of one hidden unit ---
    __shared__ float sh[64][16];

    const float* xz = g_xz + ((size_t)dir * TT + t) * BB * GG;
    float* cptr = g_c + (size_t)dir * BB * HH;
    const int u = qc >> 1;                     // unit within warp (0..1)
    const int j = nblk * 16 + warp * 2 + u;    // global hidden index
    const int lu = warp * 2 + u;               // unit within CTA (0..15)
    const bool odd = qc & 1;

#pragma unroll
    for (int mt = 0; mt < 4; mt++) {
        float e0 = __shfl_xor_sync(0xffffffffu, d[mt][0], 1);
        float e1 = __shfl_xor_sync(0xffffffffu, d[mt][1], 1);
        float e2 = __shfl_xor_sync(0xffffffffu, d[mt][2], 1);
        float e3 = __shfl_xor_sync(0xffffffffu, d[mt][3], 1);
        const int b = mt * 16 + qr + (odd ? 8 : 0);

        float zi = odd ? e2 : d[mt][0];
        float zf = odd ? e3 : d[mt][1];
        float zo = odd ? d[mt][2] : e0;
        float zg = odd ? d[mt][3] : e1;

        const float4 xv = *(const float4*)(xz + (size_t)b * GG + j * 4);
        zi += xv.x; zf += xv.y; zo += xv.z; zg += xv.w;

        const float ig = 1.0f / (1.0f + __expf(-zi));
        const float fg = 1.0f / (1.0f + __expf(-zf));
        const float og = 1.0f / (1.0f + __expf(-zo));
        const float gt = tanhf(zg);

        const size_t ci = (size_t)b * HH + j;
        const float cn = fg * cptr[ci] + ig * gt;
        const float hn = og * tanhf(cn);
        cptr[ci] = cn;
        out[(((size_t)b * TT + t) * 2 + dir) * HH + j] = hn;
        sh[b][lu] = hn;
    }
    __syncthreads();

    // --- Write h (hi/lo fp16) rows for next step's A, parity pw ---
    const int tid = threadIdx.x;
    if (tid < 128) {
        const int b = tid & 63;
        const int mat = tid >> 6;
        __half* dst = g_A + ((size_t)(pw * 2 + dir) * 2 + mat) * 65536 +
                      (size_t)b * 1024 + nblk * 16;
        __half tmp[16];
#pragma unroll
        for (int q = 0; q < 16; q++) {
            float h = sh[b][q];
            __half hh = __float2half_rn(h);
            tmp[q] = mat ? __float2half_rn(h - __half2float(hh)) : hh;
        }
        *(uint4*)(dst)     = *(uint4*)(tmp);
        *(uint4*)(dst + 8) = *(uint4*)(tmp + 8);
    }
}

// ---------------------------------------------------------------------------
// Launch
// ---------------------------------------------------------------------------
extern "C" void kernel_launch(void* const* d_in, const int* in_sizes, int n_in,
                              void* d_out, int out_size) {
    const float* X    = (const float*)d_in[0];
    const float* Wx_f = (const float*)d_in[1];
    const float* Wh_f = (const float*)d_in[2];
    const float* b_f  = (const float*)d_in[3];
    const float* Wx_b = (const float*)d_in[4];
    const float* Wh_b = (const float*)d_in[5];
    const float* b_b  = (const float*)d_in[6];
    float* out = (float*)d_out;

    init_kernel<<<512, 256>>>();
    conv_kernel<<<8192, 256>>>(Wh_f, Wh_b);

    dim3 pg(GG / 128, (BB * TT) / 128, 2);
    proj_kernel<<<pg, 256>>>(X, Wx_f, Wx_b, b_f, b_b);

    for (int s = 0; s < TT; s++) {
        step_kernel<<<dim3(64, 2), 256>>>(s, out);
    }
}

// round 4
// speedup vs baseline: 2.7368x; 2.7368x over previous
#include <cuda_runtime.h>
#include <cuda_fp16.h>
#include <math.h>
#include <stdint.h>

#define BB 64      // batch
#define TT 512     // seq len
#define DD 512     // input size
#define HH 1024    // hidden size
#define GG 4096    // 4*H

// ---------------------------------------------------------------------------
// Global scratch
// ---------------------------------------------------------------------------
// xz permuted: [dir][t][b][p] with p = j*4 + g (gate-interleaved)
__device__ float g_xz[(size_t)2 * TT * BB * GG];
// Wh fp16 split, fragment-native order for mma.sync m16n8k16 B operand:
// [dir][mat(hi/lo)][ntile(512)][kc16(64)][lane(32)] : uint2 (4 halfs)
__device__ uint2 g_Wfrag[(size_t)2 * 2 * 512 * 64 * 32];
// h fp16 split, chunked: [parity][dir][mat][c32(32)][b(64)] rows of 80B
// (row = 32 halfs data (64B) + 16B pad). MAT stride = 32*64*80 bytes.
__device__ __align__(16) char g_A[(size_t)2 * 2 * 2 * 32 * 64 * 80];
// cell state: [dir][b][j]
__device__ float g_c[2 * BB * HH];

#define A_MATS ((size_t)32 * 64 * 80)

// ---------------------------------------------------------------------------
#define MMA16816(d, a0, a1, a2, a3, b0, b1)                                  \
    asm volatile(                                                            \
        "mma.sync.aligned.m16n8k16.row.col.f32.f16.f16.f32 "                 \
        "{%0,%1,%2,%3}, {%4,%5,%6,%7}, {%8,%9}, {%0,%1,%2,%3};"              \
        : "+f"((d)[0]), "+f"((d)[1]), "+f"((d)[2]), "+f"((d)[3])             \
        : "r"(a0), "r"(a1), "r"(a2), "r"(a3), "r"(b0), "r"(b1))

#define LDSM_X4(r0, r1, r2, r3, addr)                                        \
    asm volatile(                                                            \
        "ldmatrix.sync.aligned.m8n8.x4.shared.b16 {%0,%1,%2,%3}, [%4];"      \
        : "=r"(r0), "=r"(r1), "=r"(r2), "=r"(r3) : "r"(addr))

__device__ __forceinline__ uint32_t smem_u32(const void* p) {
    uint32_t a;
    asm("{ .reg .u64 t; cvta.to.shared.u64 t, %1; cvt.u32.u64 %0, t; }"
        : "=r"(a) : "l"(p));
    return a;
}

// ---------------------------------------------------------------------------
// Init: zero c and all of g_A
// ---------------------------------------------------------------------------
__global__ void init_kernel() {
    int i = blockIdx.x * blockDim.x + threadIdx.x;   // 0..327679
    ((uint32_t*)g_A)[i] = 0u;
    if (i < 2 * BB * HH) g_c[i] = 0.0f;
}

// ---------------------------------------------------------------------------
// Weight conversion: Wh fp32 -> fp16 hi/lo in B-fragment order (one-time).
// ---------------------------------------------------------------------------
__global__ void conv_kernel(const float* __restrict__ Whf,
                            const float* __restrict__ Whb) {
    int idx = blockIdx.x * blockDim.x + threadIdx.x;   // 0 .. 2^21-1
    int lane = idx & 31;
    int kc   = (idx >> 5) & 63;
    int nt   = (idx >> 11) & 511;
    int dir  = idx >> 20;
    const float* W = dir ? Whb : Whf;

    int p   = nt * 8 + (lane >> 2);          // permuted col
    int col = ((p & 3) << 10) + (p >> 2);    // original gate-major col
    int k0  = kc * 16 + (lane & 3) * 2;

    float w0 = W[(size_t)(k0)     * GG + col];
    float w1 = W[(size_t)(k0 + 1) * GG + col];
    float w2 = W[(size_t)(k0 + 8) * GG + col];
    float w3 = W[(size_t)(k0 + 9) * GG + col];

    __half h0 = __float2half_rn(w0), h1 = __float2half_rn(w1);
    __half h2 = __float2half_rn(w2), h3 = __float2half_rn(w3);
    __half l0 = __float2half_rn(w0 - __half2float(h0));
    __half l1 = __float2half_rn(w1 - __half2float(h1));
    __half l2 = __float2half_rn(w2 - __half2float(h2));
    __half l3 = __float2half_rn(w3 - __half2float(h3));

    uint2 hi, lo;
    hi.x = (uint32_t)__half_as_ushort(h0) | ((uint32_t)__half_as_ushort(h1) << 16);
    hi.y = (uint32_t)__half_as_ushort(h2) | ((uint32_t)__half_as_ushort(h3) << 16);
    lo.x = (uint32_t)__half_as_ushort(l0) | ((uint32_t)__half_as_ushort(l1) << 16);
    lo.y = (uint32_t)__half_as_ushort(l2) | ((uint32_t)__half_as_ushort(l3) << 16);

    size_t o_hi = ((((size_t)dir * 2 + 0) * 512 + nt) * 64 + kc) * 32 + lane;
    size_t o_lo = ((((size_t)dir * 2 + 1) * 512 + nt) * 64 + kc) * 32 + lane;
    g_Wfrag[o_hi] = hi;
    g_Wfrag[o_lo] = lo;
}

// ---------------------------------------------------------------------------
// Input projection (fp32 SGEMM, permuted epilogue -> g_xz)
// ---------------------------------------------------------------------------
__global__ void proj_kernel(const float* __restrict__ X,
                            const float* __restrict__ Wxf,
                            const float* __restrict__ Wxb,
                            const float* __restrict__ bf,
                            const float* __restrict__ bb) {
    const int dir = blockIdx.z;
    const float* __restrict__ W    = dir ? Wxb : Wxf;
    const float* __restrict__ bias = dir ? bb : bf;
    const int n0 = blockIdx.x * 128;
    const int m0 = blockIdx.y * 128;

    __shared__ float As[8][128];
    __shared__ float Bs[8][128];

    const int tid = threadIdx.x;
    const int tx = tid & 15;
    const int ty = tid >> 4;
    const int arow = tid >> 1;
    const int acol = (tid & 1) << 2;
    const int bk   = tid >> 5;
    const int bcol = (tid & 31) << 2;

    float acc[8][8];
#pragma unroll
    for (int i = 0; i < 8; i++)
#pragma unroll
        for (int j = 0; j < 8; j++) acc[i][j] = 0.0f;

    for (int k0 = 0; k0 < DD; k0 += 8) {
        float4 av = *(const float4*)(X + (size_t)(m0 + arow) * DD + k0 + acol);
        As[acol + 0][arow] = av.x;
        As[acol + 1][arow] = av.y;
        As[acol + 2][arow] = av.z;
        As[acol + 3][arow] = av.w;
        *(float4*)(&Bs[bk][bcol]) =
            *(const float4*)(W + (size_t)(k0 + bk) * GG + n0 + bcol);
        __syncthreads();
#pragma unroll
        for (int kk = 0; kk < 8; kk++) {
            float a[8], b[8];
            *(float4*)(a)     = *(float4*)(&As[kk][ty * 8]);
            *(float4*)(a + 4) = *(float4*)(&As[kk][ty * 8 + 4]);
            *(float4*)(b)     = *(float4*)(&Bs[kk][tx * 8]);
            *(float4*)(b + 4) = *(float4*)(&Bs[kk][tx * 8 + 4]);
#pragma unroll
            for (int i = 0; i < 8; i++)
#pragma unroll
                for (int j = 0; j < 8; j++)
                    acc[i][j] = fmaf(a[i], b[j], acc[i][j]);
        }
        __syncthreads();
    }

    float bv[8];
#pragma unroll
    for (int j = 0; j < 8; j++) bv[j] = bias[n0 + tx * 8 + j];

#pragma unroll
    for (int i = 0; i < 8; i++) {
        int m  = m0 + ty * 8 + i;
        int bi = m >> 9;
        int tt = m & (TT - 1);
        float* dst = g_xz + (((size_t)dir * TT + tt) * BB + bi) * GG;
#pragma unroll
        for (int j = 0; j < 8; j++) {
            int nf = n0 + tx * 8 + j;                   // gate-major col
            int p  = ((nf & 1023) << 2) | (nf >> 10);   // permuted col
            dst[p] = acc[i][j] + bv[j];
        }
    }
}

// ---------------------------------------------------------------------------
// Recurrence step: mma.sync fp16 3-term split, smem-staged A.
// grid (64, 2), 256 threads. CTA = 64 permuted cols (16 units); warp = 8 cols.
// ---------------------------------------------------------------------------
__global__ void __launch_bounds__(256, 1) step_kernel(int s, float* __restrict__ out) {
    __shared__ __align__(16) char sA[2 * 10240];   // 2 slots x 2 mats x 64 rows x 80B
    __shared__ float sh[64][17];

    const int dir  = blockIdx.y;
    const int nblk = blockIdx.x;
    const int t  = dir ? (TT - 1 - s) : s;
    const int pr = s & 1;
    const int pw = pr ^ 1;
    const int tid  = threadIdx.x;
    const int warp = tid >> 5;
    const int lane = tid & 31;
    const int qr = lane >> 2;
    const int qc = lane & 3;
    const int ntg = nblk * 8 + warp;

    const uint2* Bh = g_Wfrag + (((size_t)(dir * 2 + 0) * 512 + ntg) * 64) * 32 + lane;
    const uint2* Bl = g_Wfrag + (((size_t)(dir * 2 + 1) * 512 + ntg) * 64) * 32 + lane;
    const char* srcA = g_A + (size_t)(pr * 2 + dir) * 2 * A_MATS;

    // Epilogue identity: lanes pair (xor 1); unit u within warp, hidden index j
    const int u = qc >> 1;
    const int j = nblk * 16 + warp * 2 + u;
    const bool odd = qc & 1;

    // Prefetch xz (cold DRAM) and c early — hidden under the mma loop.
    const float* xz = g_xz + ((size_t)dir * TT + t) * BB * GG;
    float* cptr = g_c + (size_t)dir * BB * HH;
    float4 xv[4];
    float cv[4];
#pragma unroll
    for (int mt = 0; mt < 4; mt++) {
        const int b = mt * 16 + qr + (odd ? 8 : 0);
        xv[mt] = *(const float4*)(xz + (size_t)b * GG + j * 4);
        cv[mt] = cptr[(size_t)b * HH + j];
    }

    const uint32_t sA0 = smem_u32(sA);

    // Cooperative stage of chunk c32 into slot (c32&1): 512 x 16B ops.
    auto stage = [&](int c32) {
        const int slot = (c32 & 1) * 10240;
#pragma unroll
        for (int r = 0; r < 2; r++) {
            const int idx = tid + r * 256;
            const int m = idx >> 8, rem = idx & 255, b = rem >> 2, q = rem & 3;
            const char* src = srcA + (size_t)m * A_MATS +
                              ((size_t)c32 * 64 + b) * 80 + q * 16;
            const uint32_t dst = sA0 + slot + m * 5120 + b * 80 + q * 16;
            asm volatile("cp.async.cg.shared.global [%0], [%1], 16;"
                         :: "r"(dst), "l"(src));
        }
    };

    float d[4][4] = {};

    stage(0);
    asm volatile("cp.async.commit_group;" ::: "memory");

    uint2 wh0 = Bh[0], wl0 = Bl[0], wh1 = Bh[32], wl1 = Bl[32];

    for (int c = 0; c < 32; c++) {
        uint2 nh0, nl0, nh1, nl1;
        if (c < 31) {
            nh0 = Bh[(2 * c + 2) * 32];
            nl0 = Bl[(2 * c + 2) * 32];
            nh1 = Bh[(2 * c + 3) * 32];
            nl1 = Bl[(2 * c + 3) * 32];
        }
        __syncthreads();   // compute(c-1) done: safe to overwrite slot (c+1)&1
        if (c < 31) {
            stage(c + 1);
            asm volatile("cp.async.commit_group;" ::: "memory");
            asm volatile("cp.async.wait_group 1;" ::: "memory");
        } else {
            asm volatile("cp.async.wait_group 0;" ::: "memory");
        }
        __syncthreads();   // staged chunk c visible to all warps

        const uint32_t slot = sA0 + (c & 1) * 10240;
        const uint32_t lrow = (lane & 15) * 80 + ((lane >> 4) << 4);
#pragma unroll
        for (int sub = 0; sub < 2; sub++) {
            const uint2 bh = sub ? wh1 : wh0;
            const uint2 bl = sub ? wl1 : wl0;
            const uint32_t arow = slot + lrow + sub * 32;
#pragma unroll
            for (int mt = 0; mt < 4; mt++) {
                uint32_t a0, a1, a2, a3, l0, l1, l2, l3;
                LDSM_X4(a0, a1, a2, a3, arow + mt * 16 * 80);
                LDSM_X4(l0, l1, l2, l3, arow + mt * 16 * 80 + 5120);
                MMA16816(d[mt], a0, a1, a2, a3, bh.x, bh.y);
                MMA16816(d[mt], a0, a1, a2, a3, bl.x, bl.y);
                MMA16816(d[mt], l0, l1, l2, l3, bh.x, bh.y);
            }
        }
        wh0 = nh0; wl0 = nl0; wh1 = nh1; wl1 = nl1;
    }

    // --- Epilogue: pair lanes (xor 1) to gather the 4 gates of one unit ---
    const int lu = warp * 2 + u;

#pragma unroll
    for (int mt = 0; mt < 4; mt++) {
        float e0 = __shfl_xor_sync(0xffffffffu, d[mt][0], 1);
        float e1 = __shfl_xor_sync(0xffffffffu, d[mt][1], 1);
        float e2 = __shfl_xor_sync(0xffffffffu, d[mt][2], 1);
        float e3 = __shfl_xor_sync(0xffffffffu, d[mt][3], 1);
        const int b = mt * 16 + qr + (odd ? 8 : 0);

        float zi = odd ? e2 : d[mt][0];
        float zf = odd ? e3 : d[mt][1];
        float zo = odd ? d[mt][2] : e0;
        float zg = odd ? d[mt][3] : e1;

        zi += xv[mt].x; zf += xv[mt].y; zo += xv[mt].z; zg += xv[mt].w;

        const float ig = 1.0f / (1.0f + __expf(-zi));
        const float fg = 1.0f / (1.0f + __expf(-zf));
        const float og = 1.0f / (1.0f + __expf(-zo));
        const float gt = tanhf(zg);

        const float cn = fg * cv[mt] + ig * gt;
        const float hn = og * tanhf(cn);
        cptr[(size_t)b * HH + j] = cn;
        out[(((size_t)b * TT + t) * 2 + dir) * HH + j] = hn;
        sh[b][lu] = hn;
    }
    __syncthreads();

    // --- Write h (hi/lo fp16) for next step, chunked layout, parity pw ---
    if (tid < 128) {
        const int b = tid & 63;
        const int mat = tid >> 6;
        char* dst = g_A + ((size_t)(pw * 2 + dir) * 2 + mat) * A_MATS +
                    ((size_t)(nblk >> 1) * 64 + b) * 80 + (nblk & 1) * 32;
        __half tmp[16];
#pragma unroll
        for (int q = 0; q < 16; q++) {
            float h = sh[b][q];
            __half hh = __float2half_rn(h);
            tmp[q] = mat ? __float2half_rn(h - __half2float(hh)) : hh;
        }
        *(uint4*)(dst)      = *(uint4*)(tmp);
        *(uint4*)(dst + 16) = *(uint4*)(tmp + 8);
    }
}

// ---------------------------------------------------------------------------
// Launch
// ---------------------------------------------------------------------------
extern "C" void kernel_launch(void* const* d_in, const int* in_sizes, int n_in,
                              void* d_out, int out_size) {
    const float* X    = (const float*)d_in[0];
    const float* Wx_f = (const float*)d_in[1];
    const float* Wh_f = (const float*)d_in[2];
    const float* b_f  = (const float*)d_in[3];
    const float* Wx_b = (const float*)d_in[4];
    const float* Wh_b = (const float*)d_in[5];
    const float* b_b  = (const float*)d_in[6];
    float* out = (float*)d_out;

    init_kernel<<<1280, 256>>>();
    conv_kernel<<<8192, 256>>>(Wh_f, Wh_b);

    dim3 pg(GG / 128, (BB * TT) / 128, 2);
    proj_kernel<<<pg, 256>>>(X, Wx_f, Wx_b, b_f, b_b);

    for (int s = 0; s < TT; s++) {
        step_kernel<<<dim3(64, 2), 256>>>(s, out);
    }
}

// round 5
// speedup vs baseline: 3.9919x; 1.4586x over previous
#include <cuda_runtime.h>
#include <cuda_fp16.h>
#include <math.h>
#include <stdint.h>

#define BB 64      // batch
#define TT 512     // seq len
#define DD 512     // input size
#define HH 1024    // hidden size
#define GG 4096    // 4*H

// ---------------------------------------------------------------------------
// Global scratch
// ---------------------------------------------------------------------------
// xz permuted: [dir][t][b][p] with p = j*4 + g (gate-interleaved)
__device__ float g_xz[(size_t)2 * TT * BB * GG];
// Wh fp16 split, B-fragment order: [dir][mat][nt(512)][kc16(64)][lane(32)]
__device__ uint2 g_Wfrag[(size_t)2 * 2 * 512 * 64 * 32];
// Wx fp16 split, B-fragment order: [dir][mat][nt(512)][kc16(32)][lane(32)]
__device__ uint2 g_Wxfrag[(size_t)2 * 2 * 512 * 32 * 32];
// permuted bias per dir
__device__ float g_biasp[2 * GG];
// X fp16 split: [m(32768)][k(512)]
__device__ __half g_Xh[(size_t)32768 * 512];
__device__ __half g_Xl[(size_t)32768 * 512];
// h fp16 split, chunked: [parity][dir][mat][c32(32)][b(64)] rows of 80B
__device__ __align__(16) char g_A[(size_t)2 * 2 * 2 * 32 * 64 * 80];
// cell state: [dir][b][j]
__device__ float g_c[2 * BB * HH];

#define A_MATS ((size_t)32 * 64 * 80)

// ---------------------------------------------------------------------------
#define MMA16816(d, a0, a1, a2, a3, b0, b1)                                  \
    asm volatile(                                                            \
        "mma.sync.aligned.m16n8k16.row.col.f32.f16.f16.f32 "                 \
        "{%0,%1,%2,%3}, {%4,%5,%6,%7}, {%8,%9}, {%0,%1,%2,%3};"              \
        : "+f"((d)[0]), "+f"((d)[1]), "+f"((d)[2]), "+f"((d)[3])             \
        : "r"(a0), "r"(a1), "r"(a2), "r"(a3), "r"(b0), "r"(b1))

#define LDSM_X4(r0, r1, r2, r3, addr)                                        \
    asm volatile(                                                            \
        "ldmatrix.sync.aligned.m8n8.x4.shared.b16 {%0,%1,%2,%3}, [%4];"      \
        : "=r"(r0), "=r"(r1), "=r"(r2), "=r"(r3) : "r"(addr))

#define CP16(dst, src)                                                       \
    asm volatile("cp.async.cg.shared.global [%0], [%1], 16;"                 \
                 :: "r"(dst), "l"(src))

__device__ __forceinline__ uint32_t smem_u32(const void* p) {
    uint32_t a;
    asm("{ .reg .u64 t; cvta.to.shared.u64 t, %1; cvt.u32.u64 %0, t; }"
        : "=r"(a) : "l"(p));
    return a;
}

// ---------------------------------------------------------------------------
// Init: zero c and all of g_A
// ---------------------------------------------------------------------------
__global__ void init_kernel() {
    int i = blockIdx.x * blockDim.x + threadIdx.x;   // 0..327679
    ((uint32_t*)g_A)[i] = 0u;
    if (i < 2 * BB * HH) g_c[i] = 0.0f;
}

// ---------------------------------------------------------------------------
// X fp32 -> fp16 hi/lo (rows m = b*T+t map directly, X is [B,T,D])
// ---------------------------------------------------------------------------
__global__ void convX_kernel(const float* __restrict__ X) {
    size_t idx = (size_t)blockIdx.x * blockDim.x + threadIdx.x;  // < 4M
    float4 v = ((const float4*)X)[idx];
    __half h0 = __float2half_rn(v.x), h1 = __float2half_rn(v.y);
    __half h2 = __float2half_rn(v.z), h3 = __float2half_rn(v.w);
    uint2 hi, lo;
    hi.x = (uint32_t)__half_as_ushort(h0) | ((uint32_t)__half_as_ushort(h1) << 16);
    hi.y = (uint32_t)__half_as_ushort(h2) | ((uint32_t)__half_as_ushort(h3) << 16);
    __half l0 = __float2half_rn(v.x - __half2float(h0));
    __half l1 = __float2half_rn(v.y - __half2float(h1));
    __half l2 = __float2half_rn(v.z - __half2float(h2));
    __half l3 = __float2half_rn(v.w - __half2float(h3));
    lo.x = (uint32_t)__half_as_ushort(l0) | ((uint32_t)__half_as_ushort(l1) << 16);
    lo.y = (uint32_t)__half_as_ushort(l2) | ((uint32_t)__half_as_ushort(l3) << 16);
    ((uint2*)g_Xh)[idx] = hi;
    ((uint2*)g_Xl)[idx] = lo;
}

// ---------------------------------------------------------------------------
// Wh fp32 -> fp16 hi/lo B-fragment order (K=1024 -> 64 kc)
// ---------------------------------------------------------------------------
__global__ void convW_kernel(const float* __restrict__ Whf,
                             const float* __restrict__ Whb) {
    int idx = blockIdx.x * blockDim.x + threadIdx.x;   // 0 .. 2^21-1
    int lane = idx & 31;
    int kc   = (idx >> 5) & 63;
    int nt   = (idx >> 11) & 511;
    int dir  = idx >> 20;
    const float* W = dir ? Whb : Whf;

    int p   = nt * 8 + (lane >> 2);
    int col = ((p & 3) << 10) + (p >> 2);
    int k0  = kc * 16 + (lane & 3) * 2;

    float w0 = W[(size_t)(k0)     * GG + col];
    float w1 = W[(size_t)(k0 + 1) * GG + col];
    float w2 = W[(size_t)(k0 + 8) * GG + col];
    float w3 = W[(size_t)(k0 + 9) * GG + col];

    __half h0 = __float2half_rn(w0), h1 = __float2half_rn(w1);
    __half h2 = __float2half_rn(w2), h3 = __float2half_rn(w3);
    uint2 hi, lo;
    hi.x = (uint32_t)__half_as_ushort(h0) | ((uint32_t)__half_as_ushort(h1) << 16);
    hi.y = (uint32_t)__half_as_ushort(h2) | ((uint32_t)__half_as_ushort(h3) << 16);
    lo.x = (uint32_t)__half_as_ushort(__float2half_rn(w0 - __half2float(h0))) |
           ((uint32_t)__half_as_ushort(__float2half_rn(w1 - __half2float(h1))) << 16);
    lo.y = (uint32_t)__half_as_ushort(__float2half_rn(w2 - __half2float(h2))) |
           ((uint32_t)__half_as_ushort(__float2half_rn(w3 - __half2float(h3))) << 16);

    g_Wfrag[((((size_t)dir * 2 + 0) * 512 + nt) * 64 + kc) * 32 + lane] = hi;
    g_Wfrag[((((size_t)dir * 2 + 1) * 512 + nt) * 64 + kc) * 32 + lane] = lo;
}

// ---------------------------------------------------------------------------
// Wx fp32 -> fp16 hi/lo B-fragment order (K=512 -> 32 kc) + permuted bias
// ---------------------------------------------------------------------------
__global__ void convWx_kernel(const float* __restrict__ Wxf,
                              const float* __restrict__ Wxb,
                              const float* __restrict__ bf,
                              const float* __restrict__ bb) {
    int idx = blockIdx.x * blockDim.x + threadIdx.x;   // 0 .. 2^20-1
    int lane = idx & 31;
    int kc   = (idx >> 5) & 31;
    int nt   = (idx >> 10) & 511;
    int dir  = idx >> 19;
    const float* W = dir ? Wxb : Wxf;

    int p   = nt * 8 + (lane >> 2);
    int col = ((p & 3) << 10) + (p >> 2);
    int k0  = kc * 16 + (lane & 3) * 2;

    float w0 = W[(size_t)(k0)     * GG + col];
    float w1 = W[(size_t)(k0 + 1) * GG + col];
    float w2 = W[(size_t)(k0 + 8) * GG + col];
    float w3 = W[(size_t)(k0 + 9) * GG + col];

    __half h0 = __float2half_rn(w0), h1 = __float2half_rn(w1);
    __half h2 = __float2half_rn(w2), h3 = __float2half_rn(w3);
    uint2 hi, lo;
    hi.x = (uint32_t)__half_as_ushort(h0) | ((uint32_t)__half_as_ushort(h1) << 16);
    hi.y = (uint32_t)__half_as_ushort(h2) | ((uint32_t)__half_as_ushort(h3) << 16);
    lo.x = (uint32_t)__half_as_ushort(__float2half_rn(w0 - __half2float(h0))) |
           ((uint32_t)__half_as_ushort(__float2half_rn(w1 - __half2float(h1))) << 16);
    lo.y = (uint32_t)__half_as_ushort(__float2half_rn(w2 - __half2float(h2))) |
           ((uint32_t)__half_as_ushort(__float2half_rn(w3 - __half2float(h3))) << 16);

    g_Wxfrag[((((size_t)dir * 2 + 0) * 512 + nt) * 32 + kc) * 32 + lane] = hi;
    g_Wxfrag[((((size_t)dir * 2 + 1) * 512 + nt) * 32 + kc) * 32 + lane] = lo;

    if (kc == 0 && (lane & 3) == 0) {
        const float* bias = dir ? bb : bf;
        g_biasp[dir * GG + p] = bias[col];
    }
}

// ---------------------------------------------------------------------------
// Input projection: fp16 3-term split mma. CTA tile 128m x 128n (permuted).
// grid (32 nTiles, 256 mTiles, 2 dirs), 256 threads (8 warps: 2m x 4n).
// ---------------------------------------------------------------------------
__global__ void __launch_bounds__(256, 1) proj_kernel() {
    __shared__ __align__(16) char sX[2 * 12288];   // 2 buf x 2 mat x 128 x 48B

    const int dir = blockIdx.z;
    const int n0 = blockIdx.x * 128;
    const int m0 = blockIdx.y * 128;
    const int tid = threadIdx.x;
    const int warp = tid >> 5, lane = tid & 31;
    const int wm = warp >> 2, wn = warp & 3;
    const int qr = lane >> 2, qc = lane & 3;

    const size_t MATSTRIDE = (size_t)512 * 32 * 32;
    const uint2* WX = g_Wxfrag + (size_t)dir * 2 * MATSTRIDE;
    const int ntbase = (n0 >> 3) + wn * 4;

    const uint32_t sX0 = smem_u32(sX);

    auto stage = [&](int c) {
#pragma unroll
        for (int r = 0; r < 2; r++) {
            const int idx = tid + r * 256;
            const int mat = idx >> 8, row = (idx >> 1) & 127, q = idx & 1;
            const char* src = (const char*)(mat ? g_Xl : g_Xh) +
                              (((size_t)(m0 + row) * 512 + c * 16) << 1) + q * 16;
            const uint32_t dst = sX0 + (c & 1) * 12288 + mat * 6144 + row * 48 + q * 16;
            CP16(dst, src);
        }
    };

    float d[4][4][4] = {};

    stage(0);
    asm volatile("cp.async.commit_group;" ::: "memory");

    for (int c = 0; c < 32; c++) {
        __syncthreads();
        if (c < 31) {
            stage(c + 1);
            asm volatile("cp.async.commit_group;" ::: "memory");
            asm volatile("cp.async.wait_group 1;" ::: "memory");
        } else {
            asm volatile("cp.async.wait_group 0;" ::: "memory");
        }
        __syncthreads();

        uint2 bh[4], bl[4];
#pragma unroll
        for (int nt = 0; nt < 4; nt++) {
            const size_t off = (((size_t)(ntbase + nt)) * 32 + c) * 32 + lane;
            bh[nt] = WX[off];
            bl[nt] = WX[off + MATSTRIDE];
        }

        const uint32_t slot = sX0 + (c & 1) * 12288;
        const uint32_t lrow = (lane & 15) * 48 + ((lane >> 4) << 4);
#pragma unroll
        for (int mt = 0; mt < 4; mt++) {
            const uint32_t arow = slot + (wm * 64 + mt * 16) * 48 + lrow;
            uint32_t a0, a1, a2, a3, l0, l1, l2, l3;
            LDSM_X4(a0, a1, a2, a3, arow);
            LDSM_X4(l0, l1, l2, l3, arow + 6144);
#pragma unroll
            for (int nt = 0; nt < 4; nt++) {
                MMA16816(d[mt][nt], a0, a1, a2, a3, bh[nt].x, bh[nt].y);
                MMA16816(d[mt][nt], a0, a1, a2, a3, bl[nt].x, bl[nt].y);
                MMA16816(d[mt][nt], l0, l1, l2, l3, bh[nt].x, bh[nt].y);
            }
        }
    }

    // Epilogue: add permuted bias, scatter to g_xz[dir][t][b][p]
#pragma unroll
    for (int mt = 0; mt < 4; mt++) {
#pragma unroll
        for (int nt = 0; nt < 4; nt++) {
            const int n = n0 + wn * 32 + nt * 8 + qc * 2;
            const float2 bv = *(const float2*)(g_biasp + dir * GG + n);
            const int ma = m0 + wm * 64 + mt * 16 + qr;
            const int mb = ma + 8;
            float2 v0, v1;
            v0.x = d[mt][nt][0] + bv.x; v0.y = d[mt][nt][1] + bv.y;
            v1.x = d[mt][nt][2] + bv.x; v1.y = d[mt][nt][3] + bv.y;
            *(float2*)(g_xz + (((size_t)dir * TT + (ma & 511)) * BB + (ma >> 9)) * GG + n) = v0;
            *(float2*)(g_xz + (((size_t)dir * TT + (mb & 511)) * BB + (mb >> 9)) * GG + n) = v1;
        }
    }
}

// ---------------------------------------------------------------------------
// Recurrence step: 512 threads, 16 warps = 8 ntiles x 2 k-halves.
// Each warp: 16 k32-chunks; fp32 partials reduced through smem.
// ---------------------------------------------------------------------------
__global__ void __launch_bounds__(512, 1) step_kernel(int s, float* __restrict__ out) {
    __shared__ __align__(16) char sA[2 * 20480];   // 2 buf x 2 kh x 2 mat x 64 x 80B

    const int dir  = blockIdx.y;
    const int nblk = blockIdx.x;
    const int t  = dir ? (TT - 1 - s) : s;
    const int pr = s & 1;
    const int pw = pr ^ 1;
    const int tid  = threadIdx.x;
    const int warp = tid >> 5;
    const int lane = tid & 31;
    const int ntw = warp & 7;
    const int kh  = warp >> 3;
    const int qr = lane >> 2;
    const int qc = lane & 3;
    const int ntg = nblk * 8 + ntw;

    const uint2* Bh = g_Wfrag + (((size_t)(dir * 2 + 0) * 512 + ntg) * 64) * 32 + lane;
    const uint2* Bl = g_Wfrag + (((size_t)(dir * 2 + 1) * 512 + ntg) * 64) * 32 + lane;
    const char* srcA = g_A + (size_t)(pr * 2 + dir) * 2 * A_MATS;

    const int u = qc >> 1;
    const int j = nblk * 16 + ntw * 2 + u;
    const bool odd = qc & 1;

    const float* xz = g_xz + ((size_t)dir * TT + t) * BB * GG;
    float* cptr = g_c + (size_t)dir * BB * HH;
    float4 xv[4];
    float cv[4];
    if (kh == 0) {
#pragma unroll
        for (int mt = 0; mt < 4; mt++) {
            const int b = mt * 16 + qr + (odd ? 8 : 0);
            xv[mt] = *(const float4*)(xz + (size_t)b * GG + j * 4);
            cv[mt] = cptr[(size_t)b * HH + j];
        }
    }

    const uint32_t sA0 = smem_u32(sA);

    auto stage = [&](int c) {
#pragma unroll
        for (int r = 0; r < 2; r++) {
            const int idx = tid + r * 512;
            const int khs = idx >> 9, m = (idx >> 8) & 1;
            const int b = (idx >> 2) & 63, q = idx & 3;
            const char* src = srcA + (size_t)m * A_MATS +
                              ((size_t)(khs * 16 + c) * 64 + b) * 80 + q * 16;
            const uint32_t dst = sA0 + (c & 1) * 20480 + khs * 10240 +
                                 m * 5120 + b * 80 + q * 16;
            CP16(dst, src);
        }
    };

    float d[4][4] = {};

    stage(0);
    asm volatile("cp.async.commit_group;" ::: "memory");

    uint2 wh0 = Bh[(kh * 32 + 0) * 32], wl0 = Bl[(kh * 32 + 0) * 32];
    uint2 wh1 = Bh[(kh * 32 + 1) * 32], wl1 = Bl[(kh * 32 + 1) * 32];

    for (int c = 0; c < 16; c++) {
        uint2 nh0, nl0, nh1, nl1;
        if (c < 15) {
            const int base = (kh * 32 + 2 * c + 2) * 32;
            nh0 = Bh[base];      nl0 = Bl[base];
            nh1 = Bh[base + 32]; nl1 = Bl[base + 32];
        }
        __syncthreads();
        if (c < 15) {
            stage(c + 1);
            asm volatile("cp.async.commit_group;" ::: "memory");
            asm volatile("cp.async.wait_group 1;" ::: "memory");
        } else {
            asm volatile("cp.async.wait_group 0;" ::: "memory");
        }
        __syncthreads();

        const uint32_t slot = sA0 + (c & 1) * 20480 + kh * 10240;
        const uint32_t lrow = (lane & 15) * 80 + ((lane >> 4) << 4);
#pragma unroll
        for (int sub = 0; sub < 2; sub++) {
            const uint2 bh = sub ? wh1 : wh0;
            const uint2 bl = sub ? wl1 : wl0;
            const uint32_t arow = slot + lrow + sub * 32;
#pragma unroll
            for (int mt = 0; mt < 4; mt++) {
                uint32_t a0, a1, a2, a3, l0, l1, l2, l3;
                LDSM_X4(a0, a1, a2, a3, arow + mt * 16 * 80);
                LDSM_X4(l0, l1, l2, l3, arow + mt * 16 * 80 + 5120);
                MMA16816(d[mt], a0, a1, a2, a3, bh.x, bh.y);
                MMA16816(d[mt], a0, a1, a2, a3, bl.x, bl.y);
                MMA16816(d[mt], l0, l1, l2, l3, bh.x, bh.y);
            }
        }
        wh0 = nh0; wl0 = nl0; wh1 = nh1; wl1 = nl1;
    }

    // --- Cross-k reduction: kh=1 partials -> smem -> kh=0 warps ---
    float* sred = (float*)sA;                      // [8 nt][16 reg][32 lane]
    float (*sh)[17] = (float(*)[17])(sA + 16384);  // [64 b][17]

    __syncthreads();   // all compute (LDSM reads of sA) complete
    if (kh == 1) {
#pragma unroll
        for (int mt = 0; mt < 4; mt++)
#pragma unroll
            for (int e = 0; e < 4; e++)
                sred[(ntw * 16 + mt * 4 + e) * 32 + lane] = d[mt][e];
    }
    __syncthreads();

    if (kh == 0) {
#pragma unroll
        for (int mt = 0; mt < 4; mt++)
#pragma unroll
            for (int e = 0; e < 4; e++)
                d[mt][e] += sred[(ntw * 16 + mt * 4 + e) * 32 + lane];

        const int lu = ntw * 2 + u;
#pragma unroll
        for (int mt = 0; mt < 4; mt++) {
            float e0 = __shfl_xor_sync(0xffffffffu, d[mt][0], 1);
            float e1 = __shfl_xor_sync(0xffffffffu, d[mt][1], 1);
            float e2 = __shfl_xor_sync(0xffffffffu, d[mt][2], 1);
            float e3 = __shfl_xor_sync(0xffffffffu, d[mt][3], 1);
            const int b = mt * 16 + qr + (odd ? 8 : 0);

            float zi = odd ? e2 : d[mt][0];
            float zf = odd ? e3 : d[mt][1];
            float zo = odd ? d[mt][2] : e0;
            float zg = odd ? d[mt][3] : e1;

            zi += xv[mt].x; zf += xv[mt].y; zo += xv[mt].z; zg += xv[mt].w;

            const float ig = 1.0f / (1.0f + __expf(-zi));
            const float fg = 1.0f / (1.0f + __expf(-zf));
            const float og = 1.0f / (1.0f + __expf(-zo));
            const float gt = tanhf(zg);

            const float cn = fg * cv[mt] + ig * gt;
            const float hn = og * tanhf(cn);
            cptr[(size_t)b * HH + j] = cn;
            out[(((size_t)b * TT + t) * 2 + dir) * HH + j] = hn;
            sh[b][lu] = hn;
        }
    }
    __syncthreads();

    // --- Write h (hi/lo fp16) for next step, chunked layout, parity pw ---
    if (tid < 128) {
        const int b = tid & 63;
        const int mat = tid >> 6;
        char* dst = g_A + ((size_t)(pw * 2 + dir) * 2 + mat) * A_MATS +
                    ((size_t)(nblk >> 1) * 64 + b) * 80 + (nblk & 1) * 32;
        __half tmp[16];
#pragma unroll
        for (int q = 0; q < 16; q++) {
            float h = sh[b][q];
            __half hh = __float2half_rn(h);
            tmp[q] = mat ? __float2half_rn(h - __half2float(hh)) : hh;
        }
        *(uint4*)(dst)      = *(uint4*)(tmp);
        *(uint4*)(dst + 16) = *(uint4*)(tmp + 8);
    }
}

// ---------------------------------------------------------------------------
// Launch
// ---------------------------------------------------------------------------
extern "C" void kernel_launch(void* const* d_in, const int* in_sizes, int n_in,
                              void* d_out, int out_size) {
    const float* X    = (const float*)d_in[0];
    const float* Wx_f = (const float*)d_in[1];
    const float* Wh_f = (const float*)d_in[2];
    const float* b_f  = (const float*)d_in[3];
    const float* Wx_b = (const float*)d_in[4];
    const float* Wh_b = (const float*)d_in[5];
    const float* b_b  = (const float*)d_in[6];
    float* out = (float*)d_out;

    init_kernel<<<1280, 256>>>();
    convX_kernel<<<16384, 256>>>(X);
    convW_kernel<<<8192, 256>>>(Wh_f, Wh_b);
    convWx_kernel<<<4096, 256>>>(Wx_f, Wx_b, b_f, b_b);

    proj_kernel<<<dim3(32, 256, 2), 256>>>();

    for (int s = 0; s < TT; s++) {
        step_kernel<<<dim3(64, 2), 512>>>(s, out);
    }
}